// round 3
// baseline (speedup 1.0000x reference)
#include <cuda_runtime.h>

#define BB 4
#define LL 1024
#define DD 512
#define HH 8
#define HD 64

// 128 MB scratch: S scores, overwritten in-place by normalized P.
__device__ float g_S[(size_t)BB * HH * LL * LL];
__device__ float g_wacc[BB * LL];

// ---------------------------------------------------------------------------
__global__ void zero_wacc_kernel() {
    int i = blockIdx.x * blockDim.x + threadIdx.x;
    if (i < BB * LL) g_wacc[i] = 0.f;
}

// ---------------------------------------------------------------------------
// GEMM1: S[bh][l][m] = sum_k K[b,l,h*64+k] * Q[b,m,h*64+k]
// CTA tile 128x128, kc=32 (two chunks of the K=64 reduction), 256 thr, 8x8 micro
__global__ __launch_bounds__(256) void gemm1_kernel(
    const float* __restrict__ Kp, const float* __restrict__ Qp,
    const float* __restrict__ doc)
{
    __shared__ float As[32 * 132];   // [k][row], pad stride 132
    __shared__ float Bs[32 * 132];
    int bh = blockIdx.z;
    int b = bh >> 3, h = bh & 7;
    int len = (int)doc[b];
    int l0 = blockIdx.y * 128, m0 = blockIdx.x * 128;
    if (l0 >= len || m0 >= len) return;   // tile never consumed downstream

    const float* Kb = Kp + (size_t)b * LL * DD + h * HD;
    const float* Qb = Qp + (size_t)b * LL * DD + h * HD;
    int tid = threadIdx.x;
    int tx = tid & 15, ty = tid >> 4;

    float acc[8][8];
#pragma unroll
    for (int i = 0; i < 8; i++)
#pragma unroll
        for (int j = 0; j < 8; j++) acc[i][j] = 0.f;

    for (int kc = 0; kc < 64; kc += 32) {
#pragma unroll
        for (int i = 0; i < 16; ++i) {
            int idx = tid + i * 256;           // 0..8191
            int row = idx >> 5, k = idx & 31;  // lanes: consecutive k, same row -> coalesced LDG
            As[k * 132 + row] = Kb[(size_t)(l0 + row) * DD + kc + k];
            Bs[k * 132 + row] = Qb[(size_t)(m0 + row) * DD + kc + k];
        }
        __syncthreads();
#pragma unroll
        for (int k = 0; k < 32; ++k) {
            float4 a0 = *(const float4*)&As[k * 132 + ty * 8];
            float4 a1 = *(const float4*)&As[k * 132 + ty * 8 + 4];
            float4 b0 = *(const float4*)&Bs[k * 132 + tx * 8];
            float4 b1 = *(const float4*)&Bs[k * 132 + tx * 8 + 4];
            float a[8]  = {a0.x, a0.y, a0.z, a0.w, a1.x, a1.y, a1.z, a1.w};
            float bb[8] = {b0.x, b0.y, b0.z, b0.w, b1.x, b1.y, b1.z, b1.w};
#pragma unroll
            for (int i = 0; i < 8; i++)
#pragma unroll
                for (int j = 0; j < 8; j++) acc[i][j] += a[i] * bb[j];
        }
        __syncthreads();
    }

    float* Sp = g_S + ((size_t)bh * LL + l0) * LL + m0;
#pragma unroll
    for (int i = 0; i < 8; i++) {
        int row = ty * 8 + i;
        *(float4*)&Sp[(size_t)row * LL + tx * 8] =
            make_float4(acc[i][0], acc[i][1], acc[i][2], acc[i][3]);
        *(float4*)&Sp[(size_t)row * LL + tx * 8 + 4] =
            make_float4(acc[i][4], acc[i][5], acc[i][6], acc[i][7]);
    }
}

// ---------------------------------------------------------------------------
// LN over heads + masked softmax over m + column-sum accumulation for w.
// One CTA per (b,l). Writes P in place over S.
__global__ __launch_bounds__(256) void lnsm_kernel(
    const float* __restrict__ doc, const float* __restrict__ gamma,
    const float* __restrict__ beta)
{
    __shared__ float s[HH][LL];   // 32 KB
    int b = blockIdx.y, l = blockIdx.x;
    int len = (int)doc[b];
    int tid = threadIdx.x;

    if (l >= len) {   // fully masked row -> P = 0 everywhere (softmax NaN->0)
        for (int h = 0; h < HH; ++h) {
            float* P = g_S + ((size_t)(b * HH + h) * LL + l) * LL;
            for (int m = tid; m < LL; m += 256) P[m] = 0.f;
        }
        return;
    }

    for (int h = 0; h < HH; ++h) {
        const float* Sr = g_S + ((size_t)(b * HH + h) * LL + l) * LL;
        for (int m = tid; m < len; m += 256) s[h][m] = Sr[m];
    }
    __syncthreads();

    float ga[HH], be[HH];
#pragma unroll
    for (int h = 0; h < HH; h++) { ga[h] = gamma[h]; be[h] = beta[h]; }

    // LayerNorm across heads at each (l,m)
    for (int m = tid; m < len; m += 256) {
        float x[HH]; float mu = 0.f;
#pragma unroll
        for (int h = 0; h < HH; h++) { x[h] = s[h][m]; mu += x[h]; }
        mu *= (1.f / HH);
        float var = 0.f;
#pragma unroll
        for (int h = 0; h < HH; h++) { float d0 = x[h] - mu; var += d0 * d0; }
        var *= (1.f / HH);
        float rstd = rsqrtf(var + 1e-5f);
#pragma unroll
        for (int h = 0; h < HH; h++) s[h][m] = (x[h] - mu) * rstd * ga[h] + be[h];
    }
    __syncthreads();

    // per-head masked softmax: warp w handles head w (8 warps == 8 heads)
    int w = tid >> 5, lane = tid & 31;
    {
        float mx = -1e30f;
        for (int m = lane; m < len; m += 32) mx = fmaxf(mx, s[w][m]);
#pragma unroll
        for (int o = 16; o; o >>= 1) mx = fmaxf(mx, __shfl_xor_sync(0xffffffffu, mx, o));
        float sum = 0.f;
        for (int m = lane; m < len; m += 32) {
            float e = __expf(s[w][m] - mx);
            s[w][m] = e; sum += e;
        }
#pragma unroll
        for (int o = 16; o; o >>= 1) sum += __shfl_xor_sync(0xffffffffu, sum, o);
        float inv = 1.f / sum;
        for (int m = lane; m < len; m += 32) s[w][m] *= inv;
    }
    __syncthreads();

    // write P (zeros beyond len) and accumulate column sums for w
    for (int h = 0; h < HH; ++h) {
        float* P = g_S + ((size_t)(b * HH + h) * LL + l) * LL;
        for (int m = tid; m < LL; m += 256) P[m] = (m < len) ? s[h][m] : 0.f;
    }
    for (int m = tid; m < len; m += 256) {
        float c = 0.f;
#pragma unroll
        for (int h = 0; h < HH; h++) c += s[h][m];
        atomicAdd(&g_wacc[b * LL + m], c);
    }
}

// ---------------------------------------------------------------------------
// Finalize w: scale by 1/(H*len), masked softmax over m, write [B,L].
__global__ __launch_bounds__(256) void wfin_kernel(
    const float* __restrict__ doc, float* __restrict__ wout)
{
    __shared__ float red[8];
    __shared__ float s_max, s_inv;
    int b = blockIdx.x;
    int len = (int)doc[b];
    int tid = threadIdx.x, w = tid >> 5, lane = tid & 31;
    float scale = 1.f / (8.f * (float)len);

    float mx = -1e30f;
    for (int m = tid; m < len; m += 256) mx = fmaxf(mx, g_wacc[b * LL + m]);
#pragma unroll
    for (int o = 16; o; o >>= 1) mx = fmaxf(mx, __shfl_xor_sync(0xffffffffu, mx, o));
    if (lane == 0) red[w] = mx;
    __syncthreads();
    if (tid == 0) {
        float v = red[0];
        for (int i = 1; i < 8; i++) v = fmaxf(v, red[i]);
        s_max = v * scale;   // scale > 0: max(scale*x) = scale*max(x)
    }
    __syncthreads();
    float bmax = s_max;

    float sum = 0.f;
    for (int m = tid; m < len; m += 256)
        sum += __expf(g_wacc[b * LL + m] * scale - bmax);
#pragma unroll
    for (int o = 16; o; o >>= 1) sum += __shfl_xor_sync(0xffffffffu, sum, o);
    if (lane == 0) red[w] = sum;
    __syncthreads();
    if (tid == 0) {
        float v = 0.f;
        for (int i = 0; i < 8; i++) v += red[i];
        s_inv = 1.f / v;
    }
    __syncthreads();
    float inv = s_inv;

    for (int m = tid; m < LL; m += 256)
        wout[b * LL + m] = (m < len)
            ? __expf(g_wacc[b * LL + m] * scale - bmax) * inv : 0.f;
}

// ---------------------------------------------------------------------------
// GEMM2: out[b,l,h*64+d] = sum_m P[bh][l][m] * V[b,m,h*64+d]
// CTA tile 64(M=l) x 64(N=d), kc=32, 128 thr, 8x4 micro. k-loop stops at len.
__global__ __launch_bounds__(128) void gemm2_kernel(
    const float* __restrict__ Vp, const float* __restrict__ doc,
    float* __restrict__ outp)
{
    __shared__ float Ps[32 * 68];   // [k(m)][row(l)]
    __shared__ float Vs[32 * 68];   // [k(m)][col(d)]
    int b = blockIdx.z, h = blockIdx.y;
    int len = (int)doc[b];
    int l0 = blockIdx.x * 64;
    int tid = threadIdx.x;
    int tx = tid & 15, ty = tid >> 4;

    float* outb = outp + ((size_t)b * LL + l0) * DD + h * HD;
    if (l0 >= len) {   // fully masked rows -> out tile = 0 (d_out is poisoned)
        for (int i = ty; i < 64; i += 8)
            *(float4*)&outb[(size_t)i * DD + tx * 4] = make_float4(0, 0, 0, 0);
        return;
    }

    const float* Pb = g_S + ((size_t)(b * HH + h) * LL + l0) * LL;
    const float* Vb = Vp + (size_t)b * LL * DD + h * HD;

    float acc[8][4];
#pragma unroll
    for (int i = 0; i < 8; i++)
#pragma unroll
        for (int j = 0; j < 4; j++) acc[i][j] = 0.f;

    int kend = (len + 31) & ~31;   // P columns in [len, kend) are zero
    for (int mc = 0; mc < kend; mc += 32) {
#pragma unroll
        for (int i = 0; i < 16; ++i) {
            int idx = tid + i * 128;
            int row = idx >> 5, k = idx & 31;   // coalesced over k
            Ps[k * 68 + row] = Pb[(size_t)row * LL + mc + k];
        }
#pragma unroll
        for (int i = 0; i < 16; ++i) {
            int idx = tid + i * 128;
            int k = idx >> 6, col = idx & 63;   // coalesced over col
            Vs[k * 68 + col] = Vb[(size_t)(mc + k) * DD + col];
        }
        __syncthreads();
#pragma unroll
        for (int k = 0; k < 32; ++k) {
            float4 a0 = *(const float4*)&Ps[k * 68 + ty * 8];
            float4 a1 = *(const float4*)&Ps[k * 68 + ty * 8 + 4];
            float4 b0 = *(const float4*)&Vs[k * 68 + tx * 4];
            float a[8]  = {a0.x, a0.y, a0.z, a0.w, a1.x, a1.y, a1.z, a1.w};
            float bb[4] = {b0.x, b0.y, b0.z, b0.w};
#pragma unroll
            for (int i = 0; i < 8; i++)
#pragma unroll
                for (int j = 0; j < 4; j++) acc[i][j] += a[i] * bb[j];
        }
        __syncthreads();
    }

#pragma unroll
    for (int i = 0; i < 8; i++) {
        int row = ty * 8 + i;
        *(float4*)&outb[(size_t)row * DD + tx * 4] =
            make_float4(acc[i][0], acc[i][1], acc[i][2], acc[i][3]);
    }
}

// ---------------------------------------------------------------------------
extern "C" void kernel_launch(void* const* d_in, const int* in_sizes, int n_in,
                              void* d_out, int out_size) {
    const float* K     = (const float*)d_in[0];
    const float* Q     = (const float*)d_in[1];
    const float* V     = (const float*)d_in[2];
    const float* doc   = (const float*)d_in[3];
    const float* gamma = (const float*)d_in[4];
    const float* beta  = (const float*)d_in[5];
    // d_in[6] pad_mask, d_in[7] bx_packed: fully derivable from doc_sizes; unused.

    float* outp = (float*)d_out;

    zero_wacc_kernel<<<16, 256>>>();

    dim3 g1(LL / 128, LL / 128, BB * HH);   // (8, 8, 32)
    gemm1_kernel<<<g1, 256>>>(K, Q, doc);

    dim3 g2(LL, BB);                         // one CTA per (b, l)
    lnsm_kernel<<<g2, 256>>>(doc, gamma, beta);

    if (out_size >= BB * LL * DD + BB * LL) {
        float* wout = outp + (size_t)BB * LL * DD;
        wfin_kernel<<<BB, 256>>>(doc, wout);
    }

    dim3 g3(LL / 64, HH, BB);                // (16, 8, 4)
    gemm2_kernel<<<g3, 128>>>(V, doc, outp);
}